// round 6
// baseline (speedup 1.0000x reference)
#include <cuda_runtime.h>
#include <cstdint>
#include <cstddef>

#define DIM    2048
#define BATCH  16384
#define TM     128          // == ghost-BN virtual batch
#define TN     128
#define KCB    64           // K bytes (int8 elems) per chunk
#define NCH    (DIM / KCB)  // 32
#define NSTAGE 3

// smem per-stage layout (bytes): int8 tiles, 80B row stride (64B data + pad)
#define ROWB   80
#define ST_A1  0
#define ST_A2  (ST_A1 + TM * ROWB)           // 10240
#define ST_B1  (ST_A2 + TM * ROWB)           // 20480
#define ST_B2  (ST_B1 + TN * ROWB)           // 30720
#define STAGE_SZ (ST_B2 + TN * ROWB)         // 40960
#define SMEM_TOTAL (NSTAGE * STAGE_SZ)       // 122880

// epilogue staging (reuses pipeline smem): [128][130] fp32 C + scales + stats
#define C_STRIDE 130
#define C_BYTES  (TM * C_STRIDE * 4)         // 66560
#define OFF_DA   C_BYTES                     // 128 floats
#define OFF_DB   (OFF_DA + 512)
#define OFF_SUM  (OFF_DB + 512)              // 512 floats
#define OFF_SQ   (OFF_SUM + 2048)

// ---------------- scratch ----------------
__device__ float    g_x[(size_t)BATCH * DIM];          // BN-normalized GEMM output
__device__ uint32_t g_a1[(size_t)BATCH * DIM / 4];     // feat limb1 (int8 x4)
__device__ uint32_t g_a2[(size_t)BATCH * DIM / 4];     // feat limb2
__device__ uint32_t g_b1[(size_t)DIM * DIM / 4];       // W limb1
__device__ uint32_t g_b2[(size_t)DIM * DIM / 4];       // W limb2
__device__ float    g_da[BATCH];                       // per-row scale of feat
__device__ float    g_db[DIM];                         // per-row scale of W

// ---------------- helpers ----------------
__device__ __forceinline__ uint32_t smem_u32(const void* p) {
    uint32_t a;
    asm("{ .reg .u64 t; cvta.to.shared.u64 t, %1; cvt.u32.u64 %0, t; }" : "=r"(a) : "l"(p));
    return a;
}

__device__ __forceinline__ void ldsm_x4(uint32_t* r, uint32_t addr) {
    asm volatile("ldmatrix.sync.aligned.m8n8.x4.shared.b16 {%0,%1,%2,%3}, [%4];"
                 : "=r"(r[0]), "=r"(r[1]), "=r"(r[2]), "=r"(r[3]) : "r"(addr));
}

__device__ __forceinline__ void imma(int* c, const uint32_t* a, uint32_t b0, uint32_t b1) {
    asm volatile("mma.sync.aligned.m16n8k32.row.col.s32.s8.s8.s32 "
                 "{%0,%1,%2,%3}, {%4,%5,%6,%7}, {%8,%9}, {%0,%1,%2,%3};"
                 : "+r"(c[0]), "+r"(c[1]), "+r"(c[2]), "+r"(c[3])
                 : "r"(a[0]), "r"(a[1]), "r"(a[2]), "r"(a[3]), "r"(b0), "r"(b1));
}

__device__ __forceinline__ void cp16(uint32_t dst, const void* src) {
    asm volatile("cp.async.cg.shared.global [%0], [%1], 16;" :: "r"(dst), "l"(src));
}
#define CP_COMMIT() asm volatile("cp.async.commit_group;" ::: "memory")
#define CP_WAIT1()  asm volatile("cp.async.wait_group 1;" ::: "memory")

// ================= kernel 0: per-row int8 2-limb quantization =================
// rows 0..16383: feat;  rows 16384..18431: W.  One warp per row, row in registers.
__global__ void __launch_bounds__(256)
quant_kernel(const float* __restrict__ feat, const float* __restrict__ wmat)
{
    const int lane = threadIdx.x & 31;
    const int row  = blockIdx.x * 8 + (threadIdx.x >> 5);
    const float* src;
    uint32_t *d1, *d2;
    float* dd;
    int idx;
    if (row < BATCH) { src = feat + (size_t)row * DIM; d1 = g_a1; d2 = g_a2; dd = g_da; idx = row; }
    else             { idx = row - BATCH; src = wmat + (size_t)idx * DIM; d1 = g_b1; d2 = g_b2; dd = g_db; }

    float4 v[16];
    float mx = 0.f;
    #pragma unroll
    for (int i = 0; i < 16; ++i) {
        v[i] = reinterpret_cast<const float4*>(src)[lane + i * 32];
        mx = fmaxf(mx, fmaxf(fmaxf(fabsf(v[i].x), fabsf(v[i].y)),
                             fmaxf(fabsf(v[i].z), fabsf(v[i].w))));
    }
    #pragma unroll
    for (int o = 16; o > 0; o >>= 1) mx = fmaxf(mx, __shfl_xor_sync(0xffffffffu, mx, o));
    const float delta = (mx > 0.f) ? mx * (1.f / 16000.f) : 1.f;
    const float inv = 16000.f / fmaxf(mx, 1e-30f);
    if (lane == 0) dd[idx] = delta;

    const size_t base = (size_t)idx * (DIM / 4);
    #pragma unroll
    for (int i = 0; i < 16; ++i) {
        int q0 = __float2int_rn(v[i].x * inv);
        int q1 = __float2int_rn(v[i].y * inv);
        int q2 = __float2int_rn(v[i].z * inv);
        int q3 = __float2int_rn(v[i].w * inv);
        int h0 = ((q0 + 16448) >> 7) - 128, r0 = q0 - (h0 << 7);
        int h1 = ((q1 + 16448) >> 7) - 128, r1 = q1 - (h1 << 7);
        int h2 = ((q2 + 16448) >> 7) - 128, r2 = q2 - (h2 << 7);
        int h3 = ((q3 + 16448) >> 7) - 128, r3 = q3 - (h3 << 7);
        uint32_t p1 = (h0 & 255) | ((h1 & 255) << 8) | ((h2 & 255) << 16) | ((uint32_t)(h3 & 255) << 24);
        uint32_t p2 = (r0 & 255) | ((r1 & 255) << 8) | ((r2 & 255) << 16) | ((uint32_t)(r3 & 255) << 24);
        d1[base + lane + i * 32] = p1;
        d2[base + lane + i * 32] = p2;
    }
}

// ================= kernel 1: GEMM (IMMA s8 3-pass) + fused GhostBN =================
__global__ void __launch_bounds__(512, 1)
gemm_bn_kernel(const float* __restrict__ gamma, const float* __restrict__ beta)
{
    extern __shared__ __align__(16) char smem[];
    const uint32_t sbase = smem_u32(smem);
    const int tid  = threadIdx.x;
    const int lane = tid & 31;
    const int wid  = tid >> 5;          // 0..15
    const int wm   = wid >> 3;          // warp row 0..1 (64 rows each)
    const int wn   = wid & 7;           // warp col 0..7 (16 cols each)
    const int m0   = blockIdx.y * TM;
    const int n0   = blockIdx.x * TN;

    // per-thread cp.async coordinates: each tile = 128 rows x 64B = 512 x 16B chunks
    const int cr = tid >> 2, cq = tid & 3;
    const char* pA1 = (const char*)g_a1 + (size_t)(m0 + cr) * DIM + cq * 16;
    const char* pA2 = (const char*)g_a2 + (size_t)(m0 + cr) * DIM + cq * 16;
    const char* pB1 = (const char*)g_b1 + (size_t)(n0 + cr) * DIM + cq * 16;
    const char* pB2 = (const char*)g_b2 + (size_t)(n0 + cr) * DIM + cq * 16;
    const uint32_t dOf = (uint32_t)(cr * ROWB + cq * 16);

    int acc11[4][2][4], accX[4][2][4];
    #pragma unroll
    for (int i = 0; i < 4; ++i)
        #pragma unroll
        for (int j = 0; j < 2; ++j)
            #pragma unroll
            for (int k = 0; k < 4; ++k) { acc11[i][j][k] = 0; accX[i][j][k] = 0; }

    // per-lane ldmatrix offsets (within a stage); same mapping as verified bf16 path
    const uint32_t a_off = (uint32_t)((wm * 64 + (lane & 15)) * ROWB + (lane >> 4) * 16);
    const uint32_t b_off = (uint32_t)((wn * 16 + (lane & 7) + ((lane >> 4) & 1) * 8) * ROWB
                                      + ((lane >> 3) & 1) * 16);

    // prologue: stages 0,1 in flight
    #pragma unroll
    for (int s = 0; s < 2; ++s) {
        const size_t kb = (size_t)(s * KCB);
        const uint32_t sb = sbase + s * STAGE_SZ;
        cp16(sb + ST_A1 + dOf, pA1 + kb);
        cp16(sb + ST_A2 + dOf, pA2 + kb);
        cp16(sb + ST_B1 + dOf, pB1 + kb);
        cp16(sb + ST_B2 + dOf, pB2 + kb);
        CP_COMMIT();
    }

    int s_cur = 0, s_nxt = 2;
    for (int c = 0; c < NCH; ++c) {
        CP_WAIT1();
        __syncthreads();

        if (c + 2 < NCH) {
            const size_t kb = (size_t)((c + 2) * KCB);
            const uint32_t sb = sbase + s_nxt * STAGE_SZ;
            cp16(sb + ST_A1 + dOf, pA1 + kb);
            cp16(sb + ST_A2 + dOf, pA2 + kb);
            cp16(sb + ST_B1 + dOf, pB1 + kb);
            cp16(sb + ST_B2 + dOf, pB2 + kb);
        }
        CP_COMMIT();

        const uint32_t st = sbase + s_cur * STAGE_SZ;
        #pragma unroll
        for (int ks = 0; ks < 2; ++ks) {
            const uint32_t kb = (uint32_t)(ks * 32);
            uint32_t af[4][4], b1[4], b2[4];
            #pragma unroll
            for (int mt = 0; mt < 4; ++mt) ldsm_x4(af[mt], st + ST_A1 + a_off + mt * (16 * ROWB) + kb);
            ldsm_x4(b1, st + ST_B1 + b_off + kb);
            ldsm_x4(b2, st + ST_B2 + b_off + kb);
            // P1: l1a*l1b -> S11
            #pragma unroll
            for (int mt = 0; mt < 4; ++mt)
                #pragma unroll
                for (int nt = 0; nt < 2; ++nt)
                    imma(acc11[mt][nt], af[mt], b1[nt * 2], b1[nt * 2 + 1]);
            // P2: l1a*l2b -> Scross
            #pragma unroll
            for (int mt = 0; mt < 4; ++mt)
                #pragma unroll
                for (int nt = 0; nt < 2; ++nt)
                    imma(accX[mt][nt], af[mt], b2[nt * 2], b2[nt * 2 + 1]);
            // reload af <- l2a
            #pragma unroll
            for (int mt = 0; mt < 4; ++mt) ldsm_x4(af[mt], st + ST_A2 + a_off + mt * (16 * ROWB) + kb);
            // P3: l2a*l1b -> Scross
            #pragma unroll
            for (int mt = 0; mt < 4; ++mt)
                #pragma unroll
                for (int nt = 0; nt < 2; ++nt)
                    imma(accX[mt][nt], af[mt], b1[nt * 2], b1[nt * 2 + 1]);
        }
        s_cur = (s_cur + 1) % NSTAGE;
        s_nxt = (s_nxt + 1) % NSTAGE;
    }
    __syncthreads();    // pipeline smem free; reuse for epilogue

    // ---- load per-row scales into smem ----
    float* sda = reinterpret_cast<float*>(smem + OFF_DA);
    float* sdb = reinterpret_cast<float*>(smem + OFF_DB);
    if (tid < 128)      sda[tid] = g_da[m0 + tid];
    else if (tid < 256) sdb[tid - 128] = g_db[n0 + tid - 128];
    __syncthreads();

    // ---- combine limbs, scale, stage C tile to smem ----
    float* sf = reinterpret_cast<float*>(smem);           // [128][130]
    {
        const int rbase = wm * 64 + (lane >> 2);
        const int cbase = wn * 16 + (lane & 3) * 2;
        #pragma unroll
        for (int mt = 0; mt < 4; ++mt) {
            const int r = rbase + mt * 16;
            const float da0 = sda[r], da1 = sda[r + 8];
            #pragma unroll
            for (int nt = 0; nt < 2; ++nt) {
                const int cc = cbase + nt * 8;
                const float db0 = sdb[cc], db1 = sdb[cc + 1];
                sf[r * C_STRIDE + cc]           = (16384.f * (float)acc11[mt][nt][0] + 128.f * (float)accX[mt][nt][0]) * da0 * db0;
                sf[r * C_STRIDE + cc + 1]       = (16384.f * (float)acc11[mt][nt][1] + 128.f * (float)accX[mt][nt][1]) * da0 * db1;
                sf[(r + 8) * C_STRIDE + cc]     = (16384.f * (float)acc11[mt][nt][2] + 128.f * (float)accX[mt][nt][2]) * da1 * db0;
                sf[(r + 8) * C_STRIDE + cc + 1] = (16384.f * (float)acc11[mt][nt][3] + 128.f * (float)accX[mt][nt][3]) * da1 * db1;
            }
        }
    }
    __syncthreads();

    // ---- ghost-BN stats over the 128-row tile (per column) ----
    float* s_sum = reinterpret_cast<float*>(smem + OFF_SUM);   // [512]
    float* s_sq  = reinterpret_cast<float*>(smem + OFF_SQ);    // [512]
    {
        const int col = tid & 127, part = tid >> 7;
        float sum = 0.f, sq = 0.f;
        #pragma unroll 8
        for (int r = part * 32; r < part * 32 + 32; ++r) {
            float v = sf[r * C_STRIDE + col];
            sum += v; sq += v * v;
        }
        s_sum[tid] = sum; s_sq[tid] = sq;
    }
    __syncthreads();
    if (tid < 128) {
        float sum = s_sum[tid] + s_sum[tid + 128] + s_sum[tid + 256] + s_sum[tid + 384];
        float sq  = s_sq[tid] + s_sq[tid + 128] + s_sq[tid + 256] + s_sq[tid + 384];
        float mean = sum * (1.f / 128.f);
        float var  = fmaxf(sq * (1.f / 128.f) - mean * mean, 0.f);
        float sc = gamma[n0 + tid] * rsqrtf(var + 1e-5f);
        s_sum[tid] = sc;                         // scale
        s_sq[tid]  = beta[n0 + tid] - mean * sc; // shift
    }
    __syncthreads();

    // ---- normalized write (float4) ----
    float* orow = g_x + (size_t)m0 * DIM + n0;
    #pragma unroll
    for (int i = 0; i < 8; ++i) {
        int idx = tid + i * 512;                 // 4096 float4s
        int r = idx >> 5, c4 = (idx & 31) * 4;
        float4 v;
        v.x = sf[r * C_STRIDE + c4 + 0] * s_sum[c4 + 0] + s_sq[c4 + 0];
        v.y = sf[r * C_STRIDE + c4 + 1] * s_sum[c4 + 1] + s_sq[c4 + 1];
        v.z = sf[r * C_STRIDE + c4 + 2] * s_sum[c4 + 2] + s_sq[c4 + 2];
        v.w = sf[r * C_STRIDE + c4 + 3] * s_sum[c4 + 3] + s_sq[c4 + 3];
        *reinterpret_cast<float4*>(&orow[(size_t)r * DIM + c4]) = v;
    }
}

// ================= kernel 2: sparsemax (warp-per-row Michelot) =================
__device__ __forceinline__ float warp_sum(float v) {
    #pragma unroll
    for (int o = 16; o > 0; o >>= 1) v += __shfl_xor_sync(0xffffffffu, v, o);
    return v;
}

__global__ void __launch_bounds__(256)
sparsemax_kernel(const float* __restrict__ priors, float* __restrict__ out)
{
    const int lane = threadIdx.x & 31;
    const int row  = blockIdx.x * 8 + (threadIdx.x >> 5);
    const float* xr = g_x + (size_t)row * DIM;
    const float* pr = priors + (size_t)row * DIM;

    float z[64];
    float s = 0.f;
    #pragma unroll
    for (int i = 0; i < 64; ++i) {
        int j = lane + i * 32;
        z[i] = xr[j] * pr[j];
        s += z[i];
    }
    float tau = (warp_sum(s) - 1.f) * (1.f / (float)DIM);

    for (int it = 0; it < 40; ++it) {
        float ps = 0.f, pc = 0.f;
        #pragma unroll
        for (int i = 0; i < 64; ++i)
            if (z[i] > tau) { ps += z[i]; pc += 1.f; }
        ps = warp_sum(ps); pc = warp_sum(pc);
        float tn = (ps - 1.f) / pc;
        if (tn == tau) break;        // warp-uniform (same reduced values)
        tau = tn;
    }
    #pragma unroll
    for (int i = 0; i < 64; ++i) {
        int j = lane + i * 32;
        out[(size_t)row * DIM + j] = fmaxf(z[i] - tau, 0.f);
    }
}

// ================= launch =================
extern "C" void kernel_launch(void* const* d_in, const int* in_sizes, int n_in,
                              void* d_out, int out_size)
{
    const float* priors = (const float*)d_in[0];
    const float* feat   = (const float*)d_in[1];
    const float* fw     = (const float*)d_in[2];
    const float* gamma  = (const float*)d_in[3];
    const float* beta   = (const float*)d_in[4];
    float* out = (float*)d_out;

    static bool attr_set = false;
    if (!attr_set) {
        cudaFuncSetAttribute(gemm_bn_kernel, cudaFuncAttributeMaxDynamicSharedMemorySize, SMEM_TOTAL);
        attr_set = true;
    }

    quant_kernel<<<(BATCH + DIM) / 8, 256>>>(feat, fw);
    dim3 grid(DIM / TN, BATCH / TM);    // (16, 128); x fastest keeps W in L2
    gemm_bn_kernel<<<grid, 512, SMEM_TOTAL>>>(gamma, beta);
    sparsemax_kernel<<<BATCH / 8, 256>>>(priors, out);
}

// round 7
// speedup vs baseline: 3.6874x; 3.6874x over previous
#include <cuda_runtime.h>
#include <cuda_fp16.h>
#include <cstdint>
#include <cstddef>

#define DIM    2048
#define BATCH  16384
#define TM     128          // == ghost-BN virtual batch
#define TN     256
#define KC     32           // K elems per chunk (fp16: 64B per row)
#define NCH    (DIM / KC)   // 64
#define NSTAGE 3

// smem per-stage layout (bytes): fp16 tiles, 80B row stride (64B data + pad)
#define ROWB   80
#define ST_AHI 0
#define ST_ALO (ST_AHI + TM * ROWB)          // 10240
#define ST_B   (ST_ALO + TM * ROWB)          // 20480
#define STAGE_SZ (ST_B + TN * ROWB)          // 40960
#define PIPE_SZ (NSTAGE * STAGE_SZ)          // 122880

// epilogue staging (reuses pipeline smem): [128][258] fp32 + 2x[512] stats
#define C_STRIDE 258
#define C_BYTES  (TM * C_STRIDE * 4)         // 132096
#define SMEM_TOTAL (C_BYTES + 4096)          // 136192 (> PIPE_SZ)

// ---------------- scratch ----------------
__device__ float g_x[(size_t)BATCH * DIM];              // BN-normalized GEMM output
__device__ uint2 g_ahi[(size_t)BATCH * DIM / 4];        // feat hi (fp16 x4)
__device__ uint2 g_alo[(size_t)BATCH * DIM / 4];        // feat lo residual
__device__ uint2 g_b[(size_t)DIM * DIM / 4];            // W (fp16 x4)

// ---------------- helpers ----------------
__device__ __forceinline__ uint32_t smem_u32(const void* p) {
    uint32_t a;
    asm("{ .reg .u64 t; cvta.to.shared.u64 t, %1; cvt.u32.u64 %0, t; }" : "=r"(a) : "l"(p));
    return a;
}

__device__ __forceinline__ void ldsm_x4(uint32_t* r, uint32_t addr) {
    asm volatile("ldmatrix.sync.aligned.m8n8.x4.shared.b16 {%0,%1,%2,%3}, [%4];"
                 : "=r"(r[0]), "=r"(r[1]), "=r"(r[2]), "=r"(r[3]) : "r"(addr));
}

__device__ __forceinline__ void mma_f16(float* c, const uint32_t* a, uint32_t b0, uint32_t b1) {
    asm volatile("mma.sync.aligned.m16n8k16.row.col.f32.f16.f16.f32 "
                 "{%0,%1,%2,%3}, {%4,%5,%6,%7}, {%8,%9}, {%0,%1,%2,%3};"
                 : "+f"(c[0]), "+f"(c[1]), "+f"(c[2]), "+f"(c[3])
                 : "r"(a[0]), "r"(a[1]), "r"(a[2]), "r"(a[3]), "r"(b0), "r"(b1));
}

__device__ __forceinline__ void cp16(uint32_t dst, const void* src) {
    asm volatile("cp.async.cg.shared.global [%0], [%1], 16;" :: "r"(dst), "l"(src));
}
#define CP_COMMIT() asm volatile("cp.async.commit_group;" ::: "memory")
#define CP_WAIT1()  asm volatile("cp.async.wait_group 1;" ::: "memory")

__device__ __forceinline__ uint32_t h2u(__half2 h) {
    return *reinterpret_cast<uint32_t*>(&h);
}

// ================= kernel 0: fp32 -> fp16 (A: hi+lo split, B: single) =================
#define FEAT_N4 ((BATCH * DIM) / 4)
#define W_N4    ((DIM * DIM) / 4)

__global__ void __launch_bounds__(256)
split_kernel(const float* __restrict__ feat, const float* __restrict__ wmat)
{
    int idx = blockIdx.x * 256 + threadIdx.x;
    if (idx < FEAT_N4) {
        float4 v = reinterpret_cast<const float4*>(feat)[idx];
        __half2 h0 = __floats2half2_rn(v.x, v.y);
        __half2 h1 = __floats2half2_rn(v.z, v.w);
        float lx = v.x - __low2float(h0);
        float ly = v.y - __high2float(h0);
        float lz = v.z - __low2float(h1);
        float lw = v.w - __high2float(h1);
        g_ahi[idx] = make_uint2(h2u(h0), h2u(h1));
        g_alo[idx] = make_uint2(h2u(__floats2half2_rn(lx, ly)), h2u(__floats2half2_rn(lz, lw)));
    } else if (idx < FEAT_N4 + W_N4) {
        int j = idx - FEAT_N4;
        float4 v = reinterpret_cast<const float4*>(wmat)[j];
        g_b[j] = make_uint2(h2u(__floats2half2_rn(v.x, v.y)), h2u(__floats2half2_rn(v.z, v.w)));
    }
}

// ================= kernel 1: GEMM (fp16 2-pass) + fused GhostBN =================
__global__ void __launch_bounds__(512, 1)
gemm_bn_kernel(const float* __restrict__ gamma, const float* __restrict__ beta)
{
    extern __shared__ __align__(16) char smem[];
    const uint32_t sbase = smem_u32(smem);
    const int tid  = threadIdx.x;
    const int lane = tid & 31;
    const int wid  = tid >> 5;          // 0..15
    const int wm   = wid >> 3;          // warp row 0..1 (64 rows each)
    const int wn   = wid & 7;           // warp col 0..7 (32 cols each)
    const int m0   = blockIdx.y * TM;
    const int n0   = blockIdx.x * TN;

    // per-thread cp.async coordinates (16B chunks; 64B per tile row per chunk)
    const int cr = tid >> 2, cq = tid & 3;                    // A: 1 chunk/thread each
    const char* pAhi = (const char*)g_ahi + ((size_t)(m0 + cr) * DIM + cq * 8) * 2;
    const char* pAlo = (const char*)g_alo + ((size_t)(m0 + cr) * DIM + cq * 8) * 2;
    const uint32_t dA = (uint32_t)(cr * ROWB + cq * 16);
    const int br0 = tid >> 2,         bq0 = tid & 3;          // B: 2 chunks/thread
    const int br1 = (tid + 512) >> 2, bq1 = tid & 3;
    const char* pB0 = (const char*)g_b + ((size_t)(n0 + br0) * DIM + bq0 * 8) * 2;
    const char* pB1 = (const char*)g_b + ((size_t)(n0 + br1) * DIM + bq1 * 8) * 2;
    const uint32_t dB0 = (uint32_t)(br0 * ROWB + bq0 * 16);
    const uint32_t dB1 = (uint32_t)(br1 * ROWB + bq1 * 16);

    float acc[4][4][4];
    #pragma unroll
    for (int i = 0; i < 4; ++i)
        #pragma unroll
        for (int j = 0; j < 4; ++j)
            #pragma unroll
            for (int k = 0; k < 4; ++k) acc[i][j][k] = 0.f;

    // per-lane ldmatrix offsets (within a stage)
    const uint32_t a_off = (uint32_t)((wm * 64 + (lane & 15)) * ROWB + (lane >> 4) * 16);
    const uint32_t b_off = (uint32_t)((wn * 32 + (lane & 7) + ((lane >> 4) & 1) * 8) * ROWB
                                      + ((lane >> 3) & 1) * 16);

    // prologue: stages 0,1 in flight
    #pragma unroll
    for (int s = 0; s < 2; ++s) {
        const size_t kb = (size_t)(s * KC) * 2;   // byte offset along K
        const uint32_t sb = sbase + s * STAGE_SZ;
        cp16(sb + ST_AHI + dA,  pAhi + kb);
        cp16(sb + ST_ALO + dA,  pAlo + kb);
        cp16(sb + ST_B + dB0,   pB0 + kb);
        cp16(sb + ST_B + dB1,   pB1 + kb);
        CP_COMMIT();
    }

    int s_cur = 0, s_nxt = 2;
    for (int c = 0; c < NCH; ++c) {
        CP_WAIT1();
        __syncthreads();                          // stage s_cur ready; stage s_nxt free

        if (c + 2 < NCH) {
            const size_t kb = (size_t)((c + 2) * KC) * 2;
            const uint32_t sb = sbase + s_nxt * STAGE_SZ;
            cp16(sb + ST_AHI + dA,  pAhi + kb);
            cp16(sb + ST_ALO + dA,  pAlo + kb);
            cp16(sb + ST_B + dB0,   pB0 + kb);
            cp16(sb + ST_B + dB1,   pB1 + kb);
        }
        CP_COMMIT();

        const uint32_t st = sbase + s_cur * STAGE_SZ;
        #pragma unroll
        for (int ks = 0; ks < 2; ++ks) {
            const uint32_t kb = (uint32_t)(ks * 32);
            uint32_t af[4][4], bb[2][4];
            #pragma unroll
            for (int mt = 0; mt < 4; ++mt) ldsm_x4(af[mt], st + ST_AHI + a_off + mt * (16 * ROWB) + kb);
            #pragma unroll
            for (int bt = 0; bt < 2; ++bt) ldsm_x4(bb[bt], st + ST_B + b_off + bt * (16 * ROWB) + kb);
            // P1: A_hi * B
            #pragma unroll
            for (int mt = 0; mt < 4; ++mt)
                #pragma unroll
                for (int nt = 0; nt < 4; ++nt)
                    mma_f16(acc[mt][nt], af[mt], bb[nt >> 1][(nt & 1) * 2], bb[nt >> 1][(nt & 1) * 2 + 1]);
            // reload af <- A_lo (same registers)
            #pragma unroll
            for (int mt = 0; mt < 4; ++mt) ldsm_x4(af[mt], st + ST_ALO + a_off + mt * (16 * ROWB) + kb);
            // P2: A_lo * B
            #pragma unroll
            for (int mt = 0; mt < 4; ++mt)
                #pragma unroll
                for (int nt = 0; nt < 4; ++nt)
                    mma_f16(acc[mt][nt], af[mt], bb[nt >> 1][(nt & 1) * 2], bb[nt >> 1][(nt & 1) * 2 + 1]);
        }
        s_cur = (s_cur + 1) % NSTAGE;
        s_nxt = (s_nxt + 1) % NSTAGE;
    }
    __syncthreads();    // pipeline smem free; reuse for epilogue

    // ---- stage C tile to smem ----
    float* sf = reinterpret_cast<float*>(smem);           // [128][258]
    {
        const int rbase = wm * 64 + (lane >> 2);
        const int cbase = wn * 32 + (lane & 3) * 2;
        #pragma unroll
        for (int mt = 0; mt < 4; ++mt)
            #pragma unroll
            for (int nt = 0; nt < 4; ++nt) {
                int r = rbase + mt * 16, cc = cbase + nt * 8;
                *reinterpret_cast<float2*>(&sf[r * C_STRIDE + cc]) =
                    make_float2(acc[mt][nt][0], acc[mt][nt][1]);
                *reinterpret_cast<float2*>(&sf[(r + 8) * C_STRIDE + cc]) =
                    make_float2(acc[mt][nt][2], acc[mt][nt][3]);
            }
    }
    __syncthreads();

    // ---- ghost-BN stats over the 128-row tile (per column) ----
    float* s_sum = reinterpret_cast<float*>(smem + C_BYTES);          // [512]
    float* s_sq  = s_sum + 512;
    {
        const int col = tid & 255, half = tid >> 8;
        float sum = 0.f, sq = 0.f;
        #pragma unroll 8
        for (int r = half * 64; r < half * 64 + 64; ++r) {
            float v = sf[r * C_STRIDE + col];
            sum += v; sq += v * v;
        }
        s_sum[tid] = sum; s_sq[tid] = sq;
    }
    __syncthreads();
    if (tid < 256) {
        float sum = s_sum[tid] + s_sum[tid + 256];
        float sq  = s_sq[tid] + s_sq[tid + 256];
        float mean = sum * (1.f / 128.f);
        float var  = fmaxf(sq * (1.f / 128.f) - mean * mean, 0.f);
        float sc = gamma[n0 + tid] * rsqrtf(var + 1e-5f);
        s_sum[tid] = sc;                         // scale
        s_sq[tid]  = beta[n0 + tid] - mean * sc; // shift
    }
    __syncthreads();

    // ---- normalized write (float4) ----
    float* orow = g_x + (size_t)m0 * DIM + n0;
    #pragma unroll
    for (int i = 0; i < 16; ++i) {
        int idx = tid + i * 512;                 // 8192 float4s
        int r = idx >> 6, c4 = (idx & 63) * 4;
        float4 v;
        v.x = sf[r * C_STRIDE + c4 + 0] * s_sum[c4 + 0] + s_sq[c4 + 0];
        v.y = sf[r * C_STRIDE + c4 + 1] * s_sum[c4 + 1] + s_sq[c4 + 1];
        v.z = sf[r * C_STRIDE + c4 + 2] * s_sum[c4 + 2] + s_sq[c4 + 2];
        v.w = sf[r * C_STRIDE + c4 + 3] * s_sum[c4 + 3] + s_sq[c4 + 3];
        *reinterpret_cast<float4*>(&orow[(size_t)r * DIM + c4]) = v;
    }
}

// ================= kernel 2: sparsemax (warp-per-row Michelot) =================
__device__ __forceinline__ float warp_sum(float v) {
    #pragma unroll
    for (int o = 16; o > 0; o >>= 1) v += __shfl_xor_sync(0xffffffffu, v, o);
    return v;
}

__global__ void __launch_bounds__(256)
sparsemax_kernel(const float* __restrict__ priors, float* __restrict__ out)
{
    const int lane = threadIdx.x & 31;
    const int row  = blockIdx.x * 8 + (threadIdx.x >> 5);
    const float* xr = g_x + (size_t)row * DIM;
    const float* pr = priors + (size_t)row * DIM;

    float z[64];
    float s = 0.f;
    #pragma unroll
    for (int i = 0; i < 64; ++i) {
        int j = lane + i * 32;
        z[i] = xr[j] * pr[j];
        s += z[i];
    }
    float tau = (warp_sum(s) - 1.f) * (1.f / (float)DIM);

    for (int it = 0; it < 40; ++it) {
        float ps = 0.f, pc = 0.f;
        #pragma unroll
        for (int i = 0; i < 64; ++i)
            if (z[i] > tau) { ps += z[i]; pc += 1.f; }
        ps = warp_sum(ps); pc = warp_sum(pc);
        float tn = (ps - 1.f) / pc;
        if (tn == tau) break;        // warp-uniform (same reduced values)
        tau = tn;
    }
    #pragma unroll
    for (int i = 0; i < 64; ++i) {
        int j = lane + i * 32;
        out[(size_t)row * DIM + j] = fmaxf(z[i] - tau, 0.f);
    }
}

// ================= launch =================
extern "C" void kernel_launch(void* const* d_in, const int* in_sizes, int n_in,
                              void* d_out, int out_size)
{
    const float* priors = (const float*)d_in[0];
    const float* feat   = (const float*)d_in[1];
    const float* fw     = (const float*)d_in[2];
    const float* gamma  = (const float*)d_in[3];
    const float* beta   = (const float*)d_in[4];
    float* out = (float*)d_out;

    static bool attr_set = false;
    if (!attr_set) {
        cudaFuncSetAttribute(gemm_bn_kernel, cudaFuncAttributeMaxDynamicSharedMemorySize, SMEM_TOTAL);
        attr_set = true;
    }

    split_kernel<<<(FEAT_N4 + W_N4 + 255) / 256, 256>>>(feat, fw);
    dim3 grid(DIM / TN, BATCH / TM);    // (8, 128); x fastest keeps W in L2
    gemm_bn_kernel<<<grid, 512, SMEM_TOTAL>>>(gamma, beta);
    sparsemax_kernel<<<BATCH / 8, 256>>>(priors, out);
}

// round 8
// speedup vs baseline: 5.6629x; 1.5357x over previous
#include <cuda_runtime.h>
#include <cuda_fp16.h>
#include <cstdint>
#include <cstddef>

#define DIM    2048
#define BATCH  16384
#define TM     128          // == ghost-BN virtual batch
#define TN     256
#define KC     32           // K elems per chunk (fp16: 64B per row)
#define NCH    (DIM / KC)   // 64
#define NSTAGE 3

// smem per-stage layout (bytes): fp16 tiles, 80B row stride (64B data + pad)
#define ROWB   80
#define ST_A   0
#define ST_B   (ST_A + TM * ROWB)            // 10240
#define STAGE_SZ (ST_B + TN * ROWB)          // 30720
#define PIPE_SZ (NSTAGE * STAGE_SZ)          // 92160

// epilogue staging (reuses pipeline smem): [128][258] fp32 + 2x[512] stats
#define C_STRIDE 258
#define C_BYTES  (TM * C_STRIDE * 4)         // 132096
#define SMEM_TOTAL (C_BYTES + 4096)          // 136192

// ---------------- scratch ----------------
__device__ float g_x[(size_t)BATCH * DIM];              // BN-normalized GEMM output
__device__ uint2 g_a[(size_t)BATCH * DIM / 4];          // feat (fp16 x4)
__device__ uint2 g_b[(size_t)DIM * DIM / 4];            // W (fp16 x4)

// ---------------- helpers ----------------
__device__ __forceinline__ uint32_t smem_u32(const void* p) {
    uint32_t a;
    asm("{ .reg .u64 t; cvta.to.shared.u64 t, %1; cvt.u32.u64 %0, t; }" : "=r"(a) : "l"(p));
    return a;
}

__device__ __forceinline__ void ldsm_x4(uint32_t* r, uint32_t addr) {
    asm volatile("ldmatrix.sync.aligned.m8n8.x4.shared.b16 {%0,%1,%2,%3}, [%4];"
                 : "=r"(r[0]), "=r"(r[1]), "=r"(r[2]), "=r"(r[3]) : "r"(addr));
}

__device__ __forceinline__ void mma_f16(float* c, const uint32_t* a, uint32_t b0, uint32_t b1) {
    asm volatile("mma.sync.aligned.m16n8k16.row.col.f32.f16.f16.f32 "
                 "{%0,%1,%2,%3}, {%4,%5,%6,%7}, {%8,%9}, {%0,%1,%2,%3};"
                 : "+f"(c[0]), "+f"(c[1]), "+f"(c[2]), "+f"(c[3])
                 : "r"(a[0]), "r"(a[1]), "r"(a[2]), "r"(a[3]), "r"(b0), "r"(b1));
}

__device__ __forceinline__ void cp16(uint32_t dst, const void* src) {
    asm volatile("cp.async.cg.shared.global [%0], [%1], 16;" :: "r"(dst), "l"(src));
}
#define CP_COMMIT() asm volatile("cp.async.commit_group;" ::: "memory")
#define CP_WAIT1()  asm volatile("cp.async.wait_group 1;" ::: "memory")

__device__ __forceinline__ uint32_t h2u(__half2 h) {
    return *reinterpret_cast<uint32_t*>(&h);
}

// ================= kernel 0: fp32 -> fp16 RN =================
#define FEAT_N4 ((BATCH * DIM) / 4)
#define W_N4    ((DIM * DIM) / 4)

__global__ void __launch_bounds__(256)
split_kernel(const float* __restrict__ feat, const float* __restrict__ wmat)
{
    int idx = blockIdx.x * 256 + threadIdx.x;
    if (idx < FEAT_N4) {
        float4 v = reinterpret_cast<const float4*>(feat)[idx];
        g_a[idx] = make_uint2(h2u(__floats2half2_rn(v.x, v.y)), h2u(__floats2half2_rn(v.z, v.w)));
    } else if (idx < FEAT_N4 + W_N4) {
        int j = idx - FEAT_N4;
        float4 v = reinterpret_cast<const float4*>(wmat)[j];
        g_b[j] = make_uint2(h2u(__floats2half2_rn(v.x, v.y)), h2u(__floats2half2_rn(v.z, v.w)));
    }
}

// ================= kernel 1: GEMM (fp16 single pass) + fused GhostBN =================
__global__ void __launch_bounds__(512, 1)
gemm_bn_kernel(const float* __restrict__ gamma, const float* __restrict__ beta)
{
    extern __shared__ __align__(16) char smem[];
    const uint32_t sbase = smem_u32(smem);
    const int tid  = threadIdx.x;
    const int lane = tid & 31;
    const int wid  = tid >> 5;          // 0..15
    const int wm   = wid >> 3;          // warp row 0..1 (64 rows each)
    const int wn   = wid & 7;           // warp col 0..7 (32 cols each)
    const int m0   = blockIdx.y * TM;
    const int n0   = blockIdx.x * TN;

    // per-thread cp.async coordinates (16B chunks; 64B per tile row per chunk)
    const int cr = tid >> 2, cq = tid & 3;                    // A: 1 chunk/thread
    const char* pA = (const char*)g_a + ((size_t)(m0 + cr) * DIM + cq * 8) * 2;
    const uint32_t dA = (uint32_t)(cr * ROWB + cq * 16);
    const int br0 = tid >> 2,         bq0 = tid & 3;          // B: 2 chunks/thread
    const int br1 = (tid + 512) >> 2, bq1 = tid & 3;
    const char* pB0 = (const char*)g_b + ((size_t)(n0 + br0) * DIM + bq0 * 8) * 2;
    const char* pB1 = (const char*)g_b + ((size_t)(n0 + br1) * DIM + bq1 * 8) * 2;
    const uint32_t dB0 = (uint32_t)(br0 * ROWB + bq0 * 16);
    const uint32_t dB1 = (uint32_t)(br1 * ROWB + bq1 * 16);

    float acc[4][4][4];
    #pragma unroll
    for (int i = 0; i < 4; ++i)
        #pragma unroll
        for (int j = 0; j < 4; ++j)
            #pragma unroll
            for (int k = 0; k < 4; ++k) acc[i][j][k] = 0.f;

    // per-lane ldmatrix offsets (within a stage)
    const uint32_t a_off = (uint32_t)((wm * 64 + (lane & 15)) * ROWB + (lane >> 4) * 16);
    const uint32_t b_off = (uint32_t)((wn * 32 + (lane & 7) + ((lane >> 4) & 1) * 8) * ROWB
                                      + ((lane >> 3) & 1) * 16);

    // prologue: stages 0,1 in flight
    #pragma unroll
    for (int s = 0; s < 2; ++s) {
        const size_t kb = (size_t)(s * KC) * 2;   // byte offset along K
        const uint32_t sb = sbase + s * STAGE_SZ;
        cp16(sb + ST_A + dA,  pA + kb);
        cp16(sb + ST_B + dB0, pB0 + kb);
        cp16(sb + ST_B + dB1, pB1 + kb);
        CP_COMMIT();
    }

    int s_cur = 0, s_nxt = 2;
    for (int c = 0; c < NCH; ++c) {
        CP_WAIT1();
        __syncthreads();                          // stage s_cur ready; stage s_nxt free

        if (c + 2 < NCH) {
            const size_t kb = (size_t)((c + 2) * KC) * 2;
            const uint32_t sb = sbase + s_nxt * STAGE_SZ;
            cp16(sb + ST_A + dA,  pA + kb);
            cp16(sb + ST_B + dB0, pB0 + kb);
            cp16(sb + ST_B + dB1, pB1 + kb);
        }
        CP_COMMIT();

        const uint32_t st = sbase + s_cur * STAGE_SZ;
        #pragma unroll
        for (int ks = 0; ks < 2; ++ks) {
            const uint32_t kb = (uint32_t)(ks * 32);
            uint32_t af[4][4], bb[2][4];
            #pragma unroll
            for (int mt = 0; mt < 4; ++mt) ldsm_x4(af[mt], st + ST_A + a_off + mt * (16 * ROWB) + kb);
            #pragma unroll
            for (int bt = 0; bt < 2; ++bt) ldsm_x4(bb[bt], st + ST_B + b_off + bt * (16 * ROWB) + kb);
            #pragma unroll
            for (int mt = 0; mt < 4; ++mt)
                #pragma unroll
                for (int nt = 0; nt < 4; ++nt)
                    mma_f16(acc[mt][nt], af[mt], bb[nt >> 1][(nt & 1) * 2], bb[nt >> 1][(nt & 1) * 2 + 1]);
        }
        s_cur = (s_cur + 1) % NSTAGE;
        s_nxt = (s_nxt + 1) % NSTAGE;
    }
    __syncthreads();    // pipeline smem free; reuse for epilogue

    // ---- stage C tile to smem ----
    float* sf = reinterpret_cast<float*>(smem);           // [128][258]
    {
        const int rbase = wm * 64 + (lane >> 2);
        const int cbase = wn * 32 + (lane & 3) * 2;
        #pragma unroll
        for (int mt = 0; mt < 4; ++mt)
            #pragma unroll
            for (int nt = 0; nt < 4; ++nt) {
                int r = rbase + mt * 16, cc = cbase + nt * 8;
                *reinterpret_cast<float2*>(&sf[r * C_STRIDE + cc]) =
                    make_float2(acc[mt][nt][0], acc[mt][nt][1]);
                *reinterpret_cast<float2*>(&sf[(r + 8) * C_STRIDE + cc]) =
                    make_float2(acc[mt][nt][2], acc[mt][nt][3]);
            }
    }
    __syncthreads();

    // ---- ghost-BN stats over the 128-row tile (per column) ----
    float* s_sum = reinterpret_cast<float*>(smem + C_BYTES);          // [512]
    float* s_sq  = s_sum + 512;
    {
        const int col = tid & 255, half = tid >> 8;
        float sum = 0.f, sq = 0.f;
        #pragma unroll 8
        for (int r = half * 64; r < half * 64 + 64; ++r) {
            float v = sf[r * C_STRIDE + col];
            sum += v; sq += v * v;
        }
        s_sum[tid] = sum; s_sq[tid] = sq;
    }
    __syncthreads();
    if (tid < 256) {
        float sum = s_sum[tid] + s_sum[tid + 256];
        float sq  = s_sq[tid] + s_sq[tid + 256];
        float mean = sum * (1.f / 128.f);
        float var  = fmaxf(sq * (1.f / 128.f) - mean * mean, 0.f);
        float sc = gamma[n0 + tid] * rsqrtf(var + 1e-5f);
        s_sum[tid] = sc;                         // scale
        s_sq[tid]  = beta[n0 + tid] - mean * sc; // shift
    }
    __syncthreads();

    // ---- normalized write (float4) ----
    float* orow = g_x + (size_t)m0 * DIM + n0;
    #pragma unroll
    for (int i = 0; i < 16; ++i) {
        int idx = tid + i * 512;                 // 8192 float4s
        int r = idx >> 6, c4 = (idx & 63) * 4;
        float4 v;
        v.x = sf[r * C_STRIDE + c4 + 0] * s_sum[c4 + 0] + s_sq[c4 + 0];
        v.y = sf[r * C_STRIDE + c4 + 1] * s_sum[c4 + 1] + s_sq[c4 + 1];
        v.z = sf[r * C_STRIDE + c4 + 2] * s_sum[c4 + 2] + s_sq[c4 + 2];
        v.w = sf[r * C_STRIDE + c4 + 3] * s_sum[c4 + 3] + s_sq[c4 + 3];
        *reinterpret_cast<float4*>(&orow[(size_t)r * DIM + c4]) = v;
    }
}

// ================= kernel 2: sparsemax (warp-per-row Michelot) =================
__device__ __forceinline__ float warp_sum(float v) {
    #pragma unroll
    for (int o = 16; o > 0; o >>= 1) v += __shfl_xor_sync(0xffffffffu, v, o);
    return v;
}

__global__ void __launch_bounds__(256)
sparsemax_kernel(const float* __restrict__ priors, float* __restrict__ out)
{
    const int lane = threadIdx.x & 31;
    const int row  = blockIdx.x * 8 + (threadIdx.x >> 5);
    const float* xr = g_x + (size_t)row * DIM;
    const float* pr = priors + (size_t)row * DIM;

    float z[64];
    float s = 0.f;
    #pragma unroll
    for (int i = 0; i < 64; ++i) {
        int j = lane + i * 32;
        z[i] = xr[j] * pr[j];
        s += z[i];
    }
    float tau = (warp_sum(s) - 1.f) * (1.f / (float)DIM);

    for (int it = 0; it < 40; ++it) {
        float ps = 0.f, pc = 0.f;
        #pragma unroll
        for (int i = 0; i < 64; ++i)
            if (z[i] > tau) { ps += z[i]; pc += 1.f; }
        ps = warp_sum(ps); pc = warp_sum(pc);
        float tn = (ps - 1.f) / pc;
        if (tn == tau) break;        // warp-uniform (same reduced values)
        tau = tn;
    }
    #pragma unroll
    for (int i = 0; i < 64; ++i) {
        int j = lane + i * 32;
        out[(size_t)row * DIM + j] = fmaxf(z[i] - tau, 0.f);
    }
}

// ================= launch =================
extern "C" void kernel_launch(void* const* d_in, const int* in_sizes, int n_in,
                              void* d_out, int out_size)
{
    const float* priors = (const float*)d_in[0];
    const float* feat   = (const float*)d_in[1];
    const float* fw     = (const float*)d_in[2];
    const float* gamma  = (const float*)d_in[3];
    const float* beta   = (const float*)d_in[4];
    float* out = (float*)d_out;

    static bool attr_set = false;
    if (!attr_set) {
        cudaFuncSetAttribute(gemm_bn_kernel, cudaFuncAttributeMaxDynamicSharedMemorySize, SMEM_TOTAL);
        attr_set = true;
    }

    split_kernel<<<(FEAT_N4 + W_N4 + 255) / 256, 256>>>(feat, fw);
    dim3 grid(DIM / TN, BATCH / TM);    // (8, 128); x fastest keeps W in L2
    gemm_bn_kernel<<<grid, 512, SMEM_TOTAL>>>(gamma, beta);
    sparsemax_kernel<<<BATCH / 8, 256>>>(priors, out);
}